// round 15
// baseline (speedup 1.0000x reference)
#include <cuda_runtime.h>
#include <cuda_fp16.h>
#include <cstdint>

// ---------------- problem dims ----------------
#define OUTF 4096
#define INF  4096
#define MROWS 8192               // 4 * 2048
#define NSPARSE 65536
#define ROWB 8192                // bytes per operand row (4096 fp16)

// ---------------- GEMM tiling ----------------
#define BM 128
#define BN 128
#define BKB 128                  // bytes per k-tile row chunk (64 fp16)
#define NKT 64                   // 4096 fp16 / 64
#define NSTG 3
#define A_BYTES (BM * BKB)       // 16384
#define B_BYTES (BN * BKB)       // 16384
#define STAGE_BYTES (A_BYTES + B_BYTES)          // 32768
#define SMEM_TOTAL (NSTG * STAGE_BYTES)          // 98304 per CTA (2 CTAs/SM)
#define NTHREADS 128

// fused prep split
#define NB_W (OUTF * 512 / 256)              // 8192 blocks (1 subvector/thread)
#define NB_X (MROWS * INF / 32 / 256)        // 4096 blocks (32 elems/thread)

// ---------------- scratch (device globals; no allocation allowed) ----------------
__device__ __half g_X[(size_t)MROWS * INF];      // 64 MB
__device__ __half g_W[(size_t)OUTF  * INF];      // 32 MB

// ---------------- helpers ----------------
__device__ __forceinline__ uint32_t smem_to_u32(const void* p) {
    uint32_t a;
    asm("{ .reg .u64 t; cvta.to.shared.u64 t, %1; cvt.u32.u64 %0, t; }" : "=r"(a) : "l"(p));
    return a;
}

__device__ __forceinline__ void cp16(uint32_t saddr, const void* g) {
    asm volatile("cp.async.cg.shared.global [%0], [%1], 16;" :: "r"(saddr), "l"(g));
}

__device__ __forceinline__ void ldsm_x4(uint32_t& r0, uint32_t& r1, uint32_t& r2, uint32_t& r3,
                                        uint32_t addr) {
    asm volatile("ldmatrix.sync.aligned.m8n8.x4.shared.b16 {%0,%1,%2,%3}, [%4];"
                 : "=r"(r0), "=r"(r1), "=r"(r2), "=r"(r3) : "r"(addr));
}

__device__ __forceinline__ void mma_f16(float* d, const uint32_t* a, uint32_t b0, uint32_t b1) {
    asm volatile(
        "mma.sync.aligned.m16n8k16.row.col.f32.f16.f16.f32 "
        "{%0,%1,%2,%3}, {%4,%5,%6,%7}, {%8,%9}, {%0,%1,%2,%3};"
        : "+f"(d[0]), "+f"(d[1]), "+f"(d[2]), "+f"(d[3])
        : "r"(a[0]), "r"(a[1]), "r"(a[2]), "r"(a[3]), "r"(b0), "r"(b1));
}

__device__ __forceinline__ uint32_t pack2h(float a, float b) {
    __half2 h = __floats2half2_rn(a, b);
    return *reinterpret_cast<uint32_t*>(&h);
}

// ---------------- prep kernels ----------------

// fused: blocks [0, NB_W) build W; blocks [NB_W, NB_W+NB_X) convert X (32 elems/thread).
__global__ void prep_kernel(const float* __restrict__ cb, const int* __restrict__ map,
                            const int* __restrict__ sva, const float* __restrict__ rn,
                            const float* __restrict__ cn, const float4* __restrict__ x) {
    int bid = blockIdx.x;
    if (bid < NB_W) {
        int t = bid * blockDim.x + threadIdx.x;      // OUTF * 512 threads
        int o = t >> 9;
        int sub = t & 511;
        int code = __ldg(map + t);
        float cw = __ldg(cn + o);
        float4 v0 = __ldg(((const float4*)cb) + code * 2);
        float4 v1 = __ldg(((const float4*)cb) + code * 2 + 1);
        int j = sub * 8;
        int4 s0 = __ldg((const int4*)(sva + j));
        int4 s1 = __ldg((const int4*)(sva + j + 4));
        __half* wrow = g_W + (size_t)o * INF;
        int c0 = s0.x;
        bool contig = ((c0 & 7) == 0) &&
                      (s0.y == c0 + 1) && (s0.z == c0 + 2) && (s0.w == c0 + 3) &&
                      (s1.x == c0 + 4) && (s1.y == c0 + 5) && (s1.z == c0 + 6) &&
                      (s1.w == c0 + 7);
        if (contig) {
            float4 r0 = __ldg((const float4*)(rn + c0));
            float4 r1 = __ldg((const float4*)(rn + c0 + 4));
            uint4 pk;
            pk.x = pack2h(v0.x * r0.x * cw, v0.y * r0.y * cw);
            pk.y = pack2h(v0.z * r0.z * cw, v0.w * r0.w * cw);
            pk.z = pack2h(v1.x * r1.x * cw, v1.y * r1.y * cw);
            pk.w = pack2h(v1.z * r1.z * cw, v1.w * r1.w * cw);
            *(uint4*)(wrow + c0) = pk;
        } else {
            float vals[8] = { v0.x, v0.y, v0.z, v0.w, v1.x, v1.y, v1.z, v1.w };
            int cols[8] = { s0.x, s0.y, s0.z, s0.w, s1.x, s1.y, s1.z, s1.w };
#pragma unroll
            for (int d = 0; d < 8; d++) {
                int col = cols[d];
                wrow[col] = __float2half_rn(vals[d] * __ldg(rn + col) * cw);
            }
        }
    } else {
        // X convert: 32 elems/thread, 8 back-to-back float4 loads (MLP=8)
        size_t t = (size_t)(bid - NB_W) * blockDim.x + threadIdx.x;
        const float4* xp = x + t * 8;
        float4 v[8];
#pragma unroll
        for (int i = 0; i < 8; i++) v[i] = __ldcs(xp + i);
        uint4 o0, o1, o2, o3;
        o0.x = pack2h(v[0].x, v[0].y); o0.y = pack2h(v[0].z, v[0].w);
        o0.z = pack2h(v[1].x, v[1].y); o0.w = pack2h(v[1].z, v[1].w);
        o1.x = pack2h(v[2].x, v[2].y); o1.y = pack2h(v[2].z, v[2].w);
        o1.z = pack2h(v[3].x, v[3].y); o1.w = pack2h(v[3].z, v[3].w);
        o2.x = pack2h(v[4].x, v[4].y); o2.y = pack2h(v[4].z, v[4].w);
        o2.z = pack2h(v[5].x, v[5].y); o2.w = pack2h(v[5].z, v[5].w);
        o3.x = pack2h(v[6].x, v[6].y); o3.y = pack2h(v[6].z, v[6].w);
        o3.z = pack2h(v[7].x, v[7].y); o3.w = pack2h(v[7].z, v[7].w);
        uint4* dst = (uint4*)(g_X + t * 32);
        dst[0] = o0;
        dst[1] = o1;
        dst[2] = o2;
        dst[3] = o3;
    }
}

// sparse outlier scatter (runs AFTER prep — matches reference overwrite order)
__global__ void sparse_scatter_kernel(const int* __restrict__ sidx,
                                      const float* __restrict__ sval) {
    int t = blockIdx.x * blockDim.x + threadIdx.x;
    if (t >= NSPARSE) return;
    int idx = sidx[t];
    g_W[idx] = __float2half_rn(sval[t]);
}

// ---------------- GEMM kernel (R12 measured-best, verbatim) ----------------
// SMEM tiles use 128B rows with swizzle: off ^ ((off>>3)&0x70)

__device__ __forceinline__ void load_tile(uint32_t sb, int stage, int kt, int m0, int n0,
                                          int tid) {
    uint32_t st = sb + (uint32_t)stage * STAGE_BYTES;
    const uint8_t* Ag = (const uint8_t*)g_X + (size_t)m0 * ROWB + (size_t)kt * BKB;
#pragma unroll
    for (int i = 0; i < 8; i++) {                      // A: 128 rows x 8 chunks of 16B
        int idx = tid + i * NTHREADS;
        int row = idx >> 3, c = idx & 7;
        uint32_t off = (uint32_t)row * 128u + (uint32_t)c * 16u;
        uint32_t sw = off ^ ((off >> 3) & 0x70);
        cp16(st + sw, Ag + (size_t)row * ROWB + c * 16);
    }
    uint32_t bt = st + A_BYTES;
    const uint8_t* Bg = (const uint8_t*)g_W + (size_t)n0 * ROWB + (size_t)kt * BKB;
#pragma unroll
    for (int i = 0; i < 8; i++) {                      // B: 128 rows x 8 chunks of 16B
        int idx = tid + i * NTHREADS;
        int row = idx >> 3, c = idx & 7;
        uint32_t off = (uint32_t)row * 128u + (uint32_t)c * 16u;
        uint32_t sw = off ^ ((off >> 3) & 0x70);
        cp16(bt + sw, Bg + (size_t)row * ROWB + c * 16);
    }
}

__global__ void __launch_bounds__(NTHREADS, 2)
gemm_kernel(const float* __restrict__ bias, float* __restrict__ out) {
    extern __shared__ char smem[];
    uint32_t sb = smem_to_u32(smem);
    const int tid  = threadIdx.x;
    const int lane = tid & 31;
    const int wid  = tid >> 5;          // 0..3
    const int wm   = wid >> 1;          // 0..1  (64 M-rows each)
    const int wn   = wid & 1;           // 0..1  (64 N-cols each)
    const int n0 = blockIdx.x * BN;
    const int m0 = blockIdx.y * BM;

    const uint32_t a_row  = (uint32_t)(wm * 64 + (lane & 15));
    const uint32_t a_mask = (a_row & 7) << 4;
    const uint32_t a_koff = (uint32_t)((lane >> 4) << 4);          // 0 or 16 bytes
    const uint32_t a_base = (a_row * 128u) ^ a_mask;               // + mt*2048 later

    const uint32_t b_row  = (uint32_t)(wn * 64 + (lane & 7) + ((lane >> 1) & 8));
    const uint32_t b_mask = (b_row & 7) << 4;
    const uint32_t b_koff = (uint32_t)((lane & 8) << 1);           // 0 or 16 bytes
    const uint32_t b_base = A_BYTES + ((b_row * 128u) ^ b_mask);   // + g*2048 later

    float acc[4][8][4];                 // mt(4 x m16) x nt(8 x n8) x 4
#pragma unroll
    for (int mt = 0; mt < 4; mt++)
#pragma unroll
        for (int nt = 0; nt < 8; nt++)
#pragma unroll
            for (int r = 0; r < 4; r++) acc[mt][nt][r] = 0.0f;

    // prologue: stages 0,1 <- tiles 0,1
    load_tile(sb, 0, 0, m0, n0, tid);
    asm volatile("cp.async.commit_group;" ::: "memory");
    load_tile(sb, 1, 1, m0, n0, tid);
    asm volatile("cp.async.commit_group;" ::: "memory");

    int stage = 0;
#pragma unroll 1
    for (int kt = 0; kt < NKT; kt++) {
        asm volatile("cp.async.wait_group 1;" ::: "memory");   // tile kt resident
        __syncthreads();   // visibility + all warps done with stage (kt+2)%3's old data

        uint32_t abase = sb + (uint32_t)stage * STAGE_BYTES + a_base;
        uint32_t bbase = sb + (uint32_t)stage * STAGE_BYTES + b_base;

#pragma unroll
        for (int ks = 0; ks < 4; ks++) {
            uint32_t kb = (uint32_t)(ks * 32);
            uint32_t a[4][4], b[4][4];
            // front: all B fragments + first A fragment
#pragma unroll
            for (int g = 0; g < 4; g++)
                ldsm_x4(b[g][0], b[g][1], b[g][2], b[g][3],
                        (bbase + (uint32_t)g * 2048) ^ (kb + b_koff));
            ldsm_x4(a[0][0], a[0][1], a[0][2], a[0][3], abase ^ (kb + a_koff));
            // interleave: prefetch a[mt+1] before the 8 MMAs that consume a[mt]
#pragma unroll
            for (int mt = 0; mt < 4; mt++) {
                if (mt < 3)
                    ldsm_x4(a[mt + 1][0], a[mt + 1][1], a[mt + 1][2], a[mt + 1][3],
                            (abase + (uint32_t)(mt + 1) * 2048) ^ (kb + a_koff));
#pragma unroll
                for (int g = 0; g < 4; g++) {
                    mma_f16(acc[mt][2 * g],     a[mt], b[g][0], b[g][1]);
                    mma_f16(acc[mt][2 * g + 1], a[mt], b[g][2], b[g][3]);
                }
            }

            // after ks=0 (tensor pipe now primed): issue next tile's loads
            if (ks == 0) {
                int kn = kt + 2;
                if (kn < NKT) {
                    int sp = stage >= 1 ? stage - 1 : 2;     // (kt+2)%3
                    load_tile(sb, sp, kn, m0, n0, tid);
                }
                asm volatile("cp.async.commit_group;" ::: "memory");  // uniform accounting
            }
        }
        stage = stage >= 2 ? 0 : stage + 1;
    }

    // ---------------- epilogue ----------------
    const int col0 = n0 + wn * 64 + (lane & 3) * 2;
    float2 bv[8];
#pragma unroll
    for (int nt = 0; nt < 8; nt++) {
        bv[nt].x = __ldg(bias + col0 + nt * 8);
        bv[nt].y = __ldg(bias + col0 + nt * 8 + 1);
    }
    const size_t row0 = (size_t)m0 + wm * 64 + (lane >> 2);
#pragma unroll
    for (int mt = 0; mt < 4; mt++) {
        float* p0 = out + (row0 + mt * 16) * OUTF;
        float* p1 = p0 + 8 * OUTF;
#pragma unroll
        for (int nt = 0; nt < 8; nt++) {
            int c = col0 + nt * 8;
            float2 v0 = { acc[mt][nt][0] + bv[nt].x, acc[mt][nt][1] + bv[nt].y };
            float2 v1 = { acc[mt][nt][2] + bv[nt].x, acc[mt][nt][3] + bv[nt].y };
            *(float2*)(p0 + c) = v0;
            *(float2*)(p1 + c) = v1;
        }
    }
}

// ---------------- launch ----------------
extern "C" void kernel_launch(void* const* d_in, const int* in_sizes, int n_in,
                              void* d_out, int out_size) {
    const float* input     = (const float*)d_in[0];   // [4,2048,4096] fp32
    const float* codebooks = (const float*)d_in[1];   // [4096,8] fp32
    const int*   mappings  = (const int*)d_in[2];     // [4096,512] i32
    const int*   sva       = (const int*)d_in[3];     // [4096] i32
    const float* rn        = (const float*)d_in[4];   // [4096] fp32 (per input-col)
    const float* cn        = (const float*)d_in[5];   // [4096] fp32 (per output-row)
    const int*   sidx      = (const int*)d_in[6];     // [65536] i32
    const float* sval      = (const float*)d_in[7];   // [65536] fp32
    const float* bias      = (const float*)d_in[8];   // [4096] fp32
    float*       out       = (float*)d_out;           // [8192,4096] fp32

    prep_kernel<<<NB_W + NB_X, 256>>>(codebooks, mappings, sva, rn, cn,
                                      (const float4*)input);
    sparse_scatter_kernel<<<NSPARSE / 256, 256>>>(sidx, sval);

    cudaFuncSetAttribute(gemm_kernel, cudaFuncAttributeMaxDynamicSharedMemorySize, SMEM_TOTAL);
    dim3 grid(OUTF / BN, MROWS / BM);   // (32, 64)
    gemm_kernel<<<grid, NTHREADS, SMEM_TOTAL>>>(bias, out);
}

// round 16
// speedup vs baseline: 1.0308x; 1.0308x over previous
#include <cuda_runtime.h>
#include <cuda_fp16.h>
#include <cstdint>

// ---------------- problem dims ----------------
#define OUTF 4096
#define INF  4096
#define MROWS 8192               // 4 * 2048
#define NSPARSE 65536
#define ROWB 8192                // bytes per operand row (4096 fp16)

// ---------------- GEMM tiling ----------------
#define BM 128
#define BN 128
#define BKB 128                  // bytes per k-tile row chunk (64 fp16)
#define NKT 64                   // 4096 fp16 / 64
#define NSTG 3
#define A_BYTES (BM * BKB)       // 16384
#define B_BYTES (BN * BKB)       // 16384
#define STAGE_BYTES (A_BYTES + B_BYTES)          // 32768
#define SMEM_TOTAL (NSTG * STAGE_BYTES)          // 98304 per CTA (2 CTAs/SM)
#define NTHREADS 128

// fused prep split: X-convert blocks first (the long half), then W-build blocks
#define NB_X (MROWS * INF / 16 / 256)        // 8192 blocks (16 elems/thread)
#define NB_W (OUTF * 512 / 256)              // 8192 blocks (1 subvector/thread)

// ---------------- scratch (device globals; no allocation allowed) ----------------
__device__ __half g_X[(size_t)MROWS * INF];      // 64 MB
__device__ __half g_W[(size_t)OUTF  * INF];      // 32 MB

// ---------------- helpers ----------------
__device__ __forceinline__ uint32_t smem_to_u32(const void* p) {
    uint32_t a;
    asm("{ .reg .u64 t; cvta.to.shared.u64 t, %1; cvt.u32.u64 %0, t; }" : "=r"(a) : "l"(p));
    return a;
}

__device__ __forceinline__ void cp16(uint32_t saddr, const void* g) {
    asm volatile("cp.async.cg.shared.global [%0], [%1], 16;" :: "r"(saddr), "l"(g));
}

__device__ __forceinline__ void ldsm_x4(uint32_t& r0, uint32_t& r1, uint32_t& r2, uint32_t& r3,
                                        uint32_t addr) {
    asm volatile("ldmatrix.sync.aligned.m8n8.x4.shared.b16 {%0,%1,%2,%3}, [%4];"
                 : "=r"(r0), "=r"(r1), "=r"(r2), "=r"(r3) : "r"(addr));
}

__device__ __forceinline__ void mma_f16(float* d, const uint32_t* a, uint32_t b0, uint32_t b1) {
    asm volatile(
        "mma.sync.aligned.m16n8k16.row.col.f32.f16.f16.f32 "
        "{%0,%1,%2,%3}, {%4,%5,%6,%7}, {%8,%9}, {%0,%1,%2,%3};"
        : "+f"(d[0]), "+f"(d[1]), "+f"(d[2]), "+f"(d[3])
        : "r"(a[0]), "r"(a[1]), "r"(a[2]), "r"(a[3]), "r"(b0), "r"(b1));
}

__device__ __forceinline__ uint32_t pack2h(float a, float b) {
    __half2 h = __floats2half2_rn(a, b);
    return *reinterpret_cast<uint32_t*>(&h);
}

// ---------------- prep kernels ----------------

// fused: blocks [0, NB_X) convert X (16 elems/thread); blocks [NB_X, NB_X+NB_W) build W.
// W-half has a vectorized fast path when the 8 assigned columns are consecutive
// and 8-aligned (true for identity subvector_assignment); scalar fallback otherwise.
__global__ void prep_kernel(const float* __restrict__ cb, const int* __restrict__ map,
                            const int* __restrict__ sva, const float* __restrict__ rn,
                            const float* __restrict__ cn, const float4* __restrict__ x) {
    int bid = blockIdx.x;
    if (bid < NB_X) {
        size_t t = (size_t)bid * blockDim.x + threadIdx.x;   // 16 elems/thread
        const float4* xp = x + t * 4;
        float4 v0 = __ldcs(xp);
        float4 v1 = __ldcs(xp + 1);
        float4 v2 = __ldcs(xp + 2);
        float4 v3 = __ldcs(xp + 3);
        uint4 o0, o1;
        o0.x = pack2h(v0.x, v0.y); o0.y = pack2h(v0.z, v0.w);
        o0.z = pack2h(v1.x, v1.y); o0.w = pack2h(v1.z, v1.w);
        o1.x = pack2h(v2.x, v2.y); o1.y = pack2h(v2.z, v2.w);
        o1.z = pack2h(v3.x, v3.y); o1.w = pack2h(v3.z, v3.w);
        uint4* dst = (uint4*)(g_X + t * 16);
        dst[0] = o0;
        dst[1] = o1;
    } else {
        int t = (bid - NB_X) * blockDim.x + threadIdx.x;     // OUTF * 512 threads
        int o = t >> 9;
        int sub = t & 511;
        int code = __ldg(map + t);
        float cw = __ldg(cn + o);
        float4 v0 = __ldg(((const float4*)cb) + code * 2);
        float4 v1 = __ldg(((const float4*)cb) + code * 2 + 1);
        int j = sub * 8;
        int4 s0 = __ldg((const int4*)(sva + j));
        int4 s1 = __ldg((const int4*)(sva + j + 4));
        __half* wrow = g_W + (size_t)o * INF;
        int c0 = s0.x;
        bool contig = ((c0 & 7) == 0) &&
                      (s0.y == c0 + 1) && (s0.z == c0 + 2) && (s0.w == c0 + 3) &&
                      (s1.x == c0 + 4) && (s1.y == c0 + 5) && (s1.z == c0 + 6) &&
                      (s1.w == c0 + 7);
        if (contig) {
            float4 r0 = __ldg((const float4*)(rn + c0));
            float4 r1 = __ldg((const float4*)(rn + c0 + 4));
            uint4 pk;
            pk.x = pack2h(v0.x * r0.x * cw, v0.y * r0.y * cw);
            pk.y = pack2h(v0.z * r0.z * cw, v0.w * r0.w * cw);
            pk.z = pack2h(v1.x * r1.x * cw, v1.y * r1.y * cw);
            pk.w = pack2h(v1.z * r1.z * cw, v1.w * r1.w * cw);
            *(uint4*)(wrow + c0) = pk;
        } else {
            float vals[8] = { v0.x, v0.y, v0.z, v0.w, v1.x, v1.y, v1.z, v1.w };
            int cols[8] = { s0.x, s0.y, s0.z, s0.w, s1.x, s1.y, s1.z, s1.w };
#pragma unroll
            for (int d = 0; d < 8; d++) {
                int col = cols[d];
                wrow[col] = __float2half_rn(vals[d] * __ldg(rn + col) * cw);
            }
        }
    }
}

// sparse outlier scatter (runs AFTER prep — matches reference overwrite order)
__global__ void sparse_scatter_kernel(const int* __restrict__ sidx,
                                      const float* __restrict__ sval) {
    int t = blockIdx.x * blockDim.x + threadIdx.x;
    if (t >= NSPARSE) return;
    int idx = sidx[t];
    g_W[idx] = __float2half_rn(sval[t]);
}

// ---------------- GEMM kernel (R12/R14 measured-best, verbatim) ----------------
// SMEM tiles use 128B rows with swizzle: off ^ ((off>>3)&0x70)

__device__ __forceinline__ void load_tile(uint32_t sb, int stage, int kt, int m0, int n0,
                                          int tid) {
    uint32_t st = sb + (uint32_t)stage * STAGE_BYTES;
    const uint8_t* Ag = (const uint8_t*)g_X + (size_t)m0 * ROWB + (size_t)kt * BKB;
#pragma unroll
    for (int i = 0; i < 8; i++) {                      // A: 128 rows x 8 chunks of 16B
        int idx = tid + i * NTHREADS;
        int row = idx >> 3, c = idx & 7;
        uint32_t off = (uint32_t)row * 128u + (uint32_t)c * 16u;
        uint32_t sw = off ^ ((off >> 3) & 0x70);
        cp16(st + sw, Ag + (size_t)row * ROWB + c * 16);
    }
    uint32_t bt = st + A_BYTES;
    const uint8_t* Bg = (const uint8_t*)g_W + (size_t)n0 * ROWB + (size_t)kt * BKB;
#pragma unroll
    for (int i = 0; i < 8; i++) {                      // B: 128 rows x 8 chunks of 16B
        int idx = tid + i * NTHREADS;
        int row = idx >> 3, c = idx & 7;
        uint32_t off = (uint32_t)row * 128u + (uint32_t)c * 16u;
        uint32_t sw = off ^ ((off >> 3) & 0x70);
        cp16(bt + sw, Bg + (size_t)row * ROWB + c * 16);
    }
}

__global__ void __launch_bounds__(NTHREADS, 2)
gemm_kernel(const float* __restrict__ bias, float* __restrict__ out) {
    extern __shared__ char smem[];
    uint32_t sb = smem_to_u32(smem);
    const int tid  = threadIdx.x;
    const int lane = tid & 31;
    const int wid  = tid >> 5;          // 0..3
    const int wm   = wid >> 1;          // 0..1  (64 M-rows each)
    const int wn   = wid & 1;           // 0..1  (64 N-cols each)
    const int n0 = blockIdx.x * BN;
    const int m0 = blockIdx.y * BM;

    const uint32_t a_row  = (uint32_t)(wm * 64 + (lane & 15));
    const uint32_t a_mask = (a_row & 7) << 4;
    const uint32_t a_koff = (uint32_t)((lane >> 4) << 4);          // 0 or 16 bytes
    const uint32_t a_base = (a_row * 128u) ^ a_mask;               // + mt*2048 later

    const uint32_t b_row  = (uint32_t)(wn * 64 + (lane & 7) + ((lane >> 1) & 8));
    const uint32_t b_mask = (b_row & 7) << 4;
    const uint32_t b_koff = (uint32_t)((lane & 8) << 1);           // 0 or 16 bytes
    const uint32_t b_base = A_BYTES + ((b_row * 128u) ^ b_mask);   // + g*2048 later

    float acc[4][8][4];                 // mt(4 x m16) x nt(8 x n8) x 4
#pragma unroll
    for (int mt = 0; mt < 4; mt++)
#pragma unroll
        for (int nt = 0; nt < 8; nt++)
#pragma unroll
            for (int r = 0; r < 4; r++) acc[mt][nt][r] = 0.0f;

    // prologue: stages 0,1 <- tiles 0,1
    load_tile(sb, 0, 0, m0, n0, tid);
    asm volatile("cp.async.commit_group;" ::: "memory");
    load_tile(sb, 1, 1, m0, n0, tid);
    asm volatile("cp.async.commit_group;" ::: "memory");

    int stage = 0;
#pragma unroll 1
    for (int kt = 0; kt < NKT; kt++) {
        asm volatile("cp.async.wait_group 1;" ::: "memory");   // tile kt resident
        __syncthreads();   // visibility + all warps done with stage (kt+2)%3's old data

        uint32_t abase = sb + (uint32_t)stage * STAGE_BYTES + a_base;
        uint32_t bbase = sb + (uint32_t)stage * STAGE_BYTES + b_base;

#pragma unroll
        for (int ks = 0; ks < 4; ks++) {
            uint32_t kb = (uint32_t)(ks * 32);
            uint32_t a[4][4], b[4][4];
            // front: all B fragments + first A fragment
#pragma unroll
            for (int g = 0; g < 4; g++)
                ldsm_x4(b[g][0], b[g][1], b[g][2], b[g][3],
                        (bbase + (uint32_t)g * 2048) ^ (kb + b_koff));
            ldsm_x4(a[0][0], a[0][1], a[0][2], a[0][3], abase ^ (kb + a_koff));
            // interleave: prefetch a[mt+1] before the 8 MMAs that consume a[mt]
#pragma unroll
            for (int mt = 0; mt < 4; mt++) {
                if (mt < 3)
                    ldsm_x4(a[mt + 1][0], a[mt + 1][1], a[mt + 1][2], a[mt + 1][3],
                            (abase + (uint32_t)(mt + 1) * 2048) ^ (kb + a_koff));
#pragma unroll
                for (int g = 0; g < 4; g++) {
                    mma_f16(acc[mt][2 * g],     a[mt], b[g][0], b[g][1]);
                    mma_f16(acc[mt][2 * g + 1], a[mt], b[g][2], b[g][3]);
                }
            }

            // after ks=0 (tensor pipe now primed): issue next tile's loads
            if (ks == 0) {
                int kn = kt + 2;
                if (kn < NKT) {
                    int sp = stage >= 1 ? stage - 1 : 2;     // (kt+2)%3
                    load_tile(sb, sp, kn, m0, n0, tid);
                }
                asm volatile("cp.async.commit_group;" ::: "memory");  // uniform accounting
            }
        }
        stage = stage >= 2 ? 0 : stage + 1;
    }

    // ---------------- epilogue ----------------
    const int col0 = n0 + wn * 64 + (lane & 3) * 2;
    float2 bv[8];
#pragma unroll
    for (int nt = 0; nt < 8; nt++) {
        bv[nt].x = __ldg(bias + col0 + nt * 8);
        bv[nt].y = __ldg(bias + col0 + nt * 8 + 1);
    }
    const size_t row0 = (size_t)m0 + wm * 64 + (lane >> 2);
#pragma unroll
    for (int mt = 0; mt < 4; mt++) {
        float* p0 = out + (row0 + mt * 16) * OUTF;
        float* p1 = p0 + 8 * OUTF;
#pragma unroll
        for (int nt = 0; nt < 8; nt++) {
            int c = col0 + nt * 8;
            float2 v0 = { acc[mt][nt][0] + bv[nt].x, acc[mt][nt][1] + bv[nt].y };
            float2 v1 = { acc[mt][nt][2] + bv[nt].x, acc[mt][nt][3] + bv[nt].y };
            *(float2*)(p0 + c) = v0;
            *(float2*)(p1 + c) = v1;
        }
    }
}

// ---------------- launch ----------------
extern "C" void kernel_launch(void* const* d_in, const int* in_sizes, int n_in,
                              void* d_out, int out_size) {
    const float* input     = (const float*)d_in[0];   // [4,2048,4096] fp32
    const float* codebooks = (const float*)d_in[1];   // [4096,8] fp32
    const int*   mappings  = (const int*)d_in[2];     // [4096,512] i32
    const int*   sva       = (const int*)d_in[3];     // [4096] i32
    const float* rn        = (const float*)d_in[4];   // [4096] fp32 (per input-col)
    const float* cn        = (const float*)d_in[5];   // [4096] fp32 (per output-row)
    const int*   sidx      = (const int*)d_in[6];     // [65536] i32
    const float* sval      = (const float*)d_in[7];   // [65536] fp32
    const float* bias      = (const float*)d_in[8];   // [4096] fp32
    float*       out       = (float*)d_out;           // [8192,4096] fp32

    prep_kernel<<<NB_X + NB_W, 256>>>(codebooks, mappings, sva, rn, cn,
                                      (const float4*)input);
    sparse_scatter_kernel<<<NSPARSE / 256, 256>>>(sidx, sval);

    cudaFuncSetAttribute(gemm_kernel, cudaFuncAttributeMaxDynamicSharedMemorySize, SMEM_TOTAL);
    dim3 grid(OUTF / BN, MROWS / BM);   // (32, 64)
    gemm_kernel<<<grid, NTHREADS, SMEM_TOTAL>>>(bias, out);
}